// round 3
// baseline (speedup 1.0000x reference)
#include <cuda_runtime.h>
#include <cuda_bf16.h>
#include <cstdint>

#define BB 32
#define NNODE 8192
#define DDIM 8
#define PPART 64
#define WWID 128
#define TTEMP 8
#define LL2 32
#define I2D 2320
#define KDIM 1024

// scratch (no allocs allowed)
__device__ __align__(256) float g_base[PPART * I2D];                // b1 + cap@W2
__device__ __align__(256) float g_h[(size_t)PPART * BB * I2D];      // h as [p][b][o]
__device__ __align__(256) float g_zp[PPART * 8 * BB * WWID];        // split-K partials [p][s][b][w]
__device__ __align__(256) float g_wx[BB * PPART * DDIM];            // [b][p][d]

__device__ __forceinline__ unsigned long long ffma2(unsigned long long a,
                                                    unsigned long long b,
                                                    unsigned long long c) {
    unsigned long long d;
    asm("fma.rn.f32x2 %0, %1, %2, %3;" : "=l"(d) : "l"(a), "l"(b), "l"(c));
    return d;
}
__device__ __forceinline__ float flo(unsigned long long v) { return __uint_as_float((unsigned)v); }
__device__ __forceinline__ float fhi(unsigned long long v) { return __uint_as_float((unsigned)(v >> 32)); }
__device__ __forceinline__ void cp16(uint32_t dst, const void* src, int szb) {
    asm volatile("cp.async.cg.shared.global [%0], [%1], 16, %2;\n" :: "r"(dst), "l"(src), "r"(szb));
}
__device__ __forceinline__ void cp_commit() { asm volatile("cp.async.commit_group;\n"); }
__device__ __forceinline__ void cp_wait1()  { asm volatile("cp.async.wait_group 1;\n"); }

#define APITCH 36
#define ABUF   (128 * APITCH)
#define BOFF   (2 * ABUF)
#define BBUF   (32 * APITCH)
#define TOFF   (BOFF + 2 * BBUF)
#define SMEMF  (TOFF + 32 * 9)

// ========== kernel 1: base[p,o] = b1 + cap(p)·W2[p,o,:] ==========
__global__ void k_base(const float* __restrict__ W2, const float* __restrict__ b1,
                       const float* __restrict__ cap) {
    int idx = blockIdx.x * 8 + (threadIdx.x >> 5);
    if (idx >= PPART * I2D) return;
    int p = idx / I2D, lane = threadIdx.x & 31;
    float4 wv = *(const float4*)(W2 + (size_t)idx * WWID + lane * 4);
    float4 cv = *(const float4*)(cap + p * WWID + lane * 4);
    float acc = wv.x * cv.x + wv.y * cv.y + wv.z * cv.z + wv.w * cv.w;
    #pragma unroll
    for (int o = 16; o > 0; o >>= 1) acc += __shfl_xor_sync(0xffffffffu, acc, o);
    if (lane == 0) g_base[idx] = acc + b1[idx];
}

// ========== kernel 2: h[p][b][o] (main GEMM, M-tile 128, N=32, K=1024) ==========
__global__ void __launch_bounds__(128, 3)
k_main(const float* __restrict__ W0, const float* __restrict__ x,
       const float* __restrict__ t, const float* __restrict__ W1,
       const int* __restrict__ nodes) {
    const int p = blockIdx.y, m0 = blockIdx.x * 128, tid = threadIdx.x;
    __shared__ __align__(16) float sm[SMEMF];
    const uint32_t smaddr = (uint32_t)__cvta_generic_to_shared(sm);

    for (int i = tid; i < BB * TTEMP; i += 128)
        sm[TOFF + (i >> 3) * 9 + (i & 7)] = t[i];

    const int lane = tid & 31, wrp = tid >> 5;
    const int lrow = lane >> 3, akk = (lane & 7) * 4;
    const float* W0p = W0 + (size_t)p * I2D * KDIM;
    const int* nodp = nodes + p * WWID;

    auto loadA = [&](int c, int buf) {
        int k0 = c * 32;
        #pragma unroll
        for (int i = 0; i < 8; i++) {
            int row = wrp * 32 + i * 4 + lrow;
            int m = m0 + row;
            int vb = (m < I2D) ? 16 : 0;
            int mc = (m < I2D) ? m : (I2D - 1);
            cp16(smaddr + (uint32_t)(buf * ABUF + row * APITCH + akk) * 4,
                 W0p + (size_t)mc * KDIM + k0 + akk, vb);
        }
    };
    auto loadB = [&](int c, int buf) {
        int k0 = c * 32;
        #pragma unroll
        for (int i = 0; i < 2; i++) {
            int b = wrp * 8 + i * 4 + lrow;
            int kk = k0 + akk;
            int node = nodp[kk >> 3];
            cp16(smaddr + (uint32_t)(BOFF + buf * BBUF + b * APITCH + akk) * 4,
                 x + (size_t)b * (NNODE * DDIM) + (size_t)node * DDIM + (kk & 7), 16);
        }
    };

    unsigned long long acc[8][4];
    #pragma unroll
    for (int i = 0; i < 8; i++)
        #pragma unroll
        for (int j = 0; j < 4; j++) acc[i][j] = 0ull;

    loadA(0, 0); loadB(0, 0); cp_commit();
    loadA(1, 1); loadB(1, 1); cp_commit();

    const int tm = tid >> 3, tn = tid & 7;
    const int NCH = KDIM / 32;
    for (int c = 0; c < NCH; c++) {
        cp_wait1();
        __syncthreads();
        const unsigned long long* Ap = (const unsigned long long*)(sm + (c & 1) * ABUF);
        const unsigned long long* Bp = (const unsigned long long*)(sm + BOFF + (c & 1) * BBUF);
        #pragma unroll
        for (int kp = 0; kp < 16; kp++) {
            unsigned long long av[8], bv[4];
            #pragma unroll
            for (int i = 0; i < 8; i++) av[i] = Ap[(tm + i * 16) * (APITCH / 2) + kp];
            #pragma unroll
            for (int j = 0; j < 4; j++) bv[j] = Bp[(tn + j * 8) * (APITCH / 2) + kp];
            #pragma unroll
            for (int i = 0; i < 8; i++)
                #pragma unroll
                for (int j = 0; j < 4; j++) acc[i][j] = ffma2(av[i], bv[j], acc[i][j]);
        }
        __syncthreads();
        if (c + 2 < NCH) { loadA(c + 2, c & 1); loadB(c + 2, c & 1); }
        cp_commit();
    }

    const float* Ts = sm + TOFF;
    #pragma unroll
    for (int i = 0; i < 8; i++) {
        int o = m0 + tm + i * 16;
        if (o >= I2D) continue;
        float bs = g_base[p * I2D + o];
        const float* w1r = W1 + (size_t)(p * I2D + o) * TTEMP;
        float4 wa = *(const float4*)(w1r);
        float4 wb = *(const float4*)(w1r + 4);
        #pragma unroll
        for (int j = 0; j < 4; j++) {
            int b = tn + j * 8;
            const float* tb = Ts + b * 9;
            float v = flo(acc[i][j]) + fhi(acc[i][j]) + bs;
            v += wa.x * tb[0] + wa.y * tb[1] + wa.z * tb[2] + wa.w * tb[3]
               + wb.x * tb[4] + wb.y * tb[5] + wb.z * tb[6] + wb.w * tb[7];
            v = v > 0.f ? v : 0.01f * v;
            g_h[(size_t)(p * BB + b) * I2D + o] = v;
        }
    }
}

// ========== kernel 3: z partials, split-K x 8, 128-byte-aligned slices ==========
// slice s: [s*288, s==7 ? 2320 : (s+1)*288)   (288 = 9*32 floats, aligned)
__global__ void __launch_bounds__(128, 3)
k_z(const float* __restrict__ W3) {
    const int s = blockIdx.x, p = blockIdx.y, tid = threadIdx.x;
    const int kbase = s * 288;
    const int kend = (s == 7) ? I2D : (kbase + 288);
    const int NCH = (s == 7) ? 10 : 9;
    __shared__ __align__(16) float sm[SMEMF];
    const uint32_t smaddr = (uint32_t)__cvta_generic_to_shared(sm);

    const int lane = tid & 31, wrp = tid >> 5;
    const int lrow = lane >> 3, akk = (lane & 7) * 4;
    const float* W3p = W3 + (size_t)p * WWID * I2D;
    const float* Hp = g_h + (size_t)p * BB * I2D;

    auto ldrow = [&](const float* basep, int row, int c, uint32_t doff) {
        int kk = kbase + c * 32 + akk;
        int vb = (kend - kk) * 4; vb = vb < 0 ? 0 : (vb > 16 ? 16 : vb);
        int kc = kk <= (I2D - 4) ? kk : (I2D - 4);   // 2316*4 bytes: 16B-aligned
        cp16(smaddr + doff * 4, basep + (size_t)row * I2D + kc, vb);
    };
    auto loadA = [&](int c, int buf) {
        #pragma unroll
        for (int i = 0; i < 8; i++) {
            int row = wrp * 32 + i * 4 + lrow;
            ldrow(W3p, row, c, (uint32_t)(buf * ABUF + row * APITCH + akk));
        }
    };
    auto loadB = [&](int c, int buf) {
        #pragma unroll
        for (int i = 0; i < 2; i++) {
            int b = wrp * 8 + i * 4 + lrow;
            ldrow(Hp, b, c, (uint32_t)(BOFF + buf * BBUF + b * APITCH + akk));
        }
    };

    unsigned long long acc[8][4];
    #pragma unroll
    for (int i = 0; i < 8; i++)
        #pragma unroll
        for (int j = 0; j < 4; j++) acc[i][j] = 0ull;

    loadA(0, 0); loadB(0, 0); cp_commit();
    loadA(1, 1); loadB(1, 1); cp_commit();

    const int tm = tid >> 3, tn = tid & 7;
    for (int c = 0; c < NCH; c++) {
        cp_wait1();
        __syncthreads();
        const unsigned long long* Ap = (const unsigned long long*)(sm + (c & 1) * ABUF);
        const unsigned long long* Bp = (const unsigned long long*)(sm + BOFF + (c & 1) * BBUF);
        #pragma unroll
        for (int kp = 0; kp < 16; kp++) {
            unsigned long long av[8], bv[4];
            #pragma unroll
            for (int i = 0; i < 8; i++) av[i] = Ap[(tm + i * 16) * (APITCH / 2) + kp];
            #pragma unroll
            for (int j = 0; j < 4; j++) bv[j] = Bp[(tn + j * 8) * (APITCH / 2) + kp];
            #pragma unroll
            for (int i = 0; i < 8; i++)
                #pragma unroll
                for (int j = 0; j < 4; j++) acc[i][j] = ffma2(av[i], bv[j], acc[i][j]);
        }
        __syncthreads();
        if (c + 2 < NCH) { loadA(c + 2, c & 1); loadB(c + 2, c & 1); }
        cp_commit();
    }

    float* zp = g_zp + (size_t)(p * 8 + s) * BB * WWID;
    #pragma unroll
    for (int i = 0; i < 8; i++) {
        int w = tm + i * 16;
        #pragma unroll
        for (int j = 0; j < 4; j++) {
            int b = tn + j * 8;
            zp[b * WWID + w] = flo(acc[i][j]) + fhi(acc[i][j]);
        }
    }
}

// ========== kernel 4: reduce partials + bias + relu + weighted gather -> wx[b][p][d] ==========
__global__ void k_wx(const float* __restrict__ x, const float* __restrict__ b3) {
    const int p = blockIdx.x, b = blockIdx.y, w = threadIdx.x;
    const int lane = w & 31, wrp = w >> 5;
    __shared__ float red[32];
    float z = b3[p * WWID + w];
    #pragma unroll
    for (int s = 0; s < 8; s++)
        z += g_zp[((size_t)(p * 8 + s) * BB + b) * WWID + w];
    z = z > 0.f ? z : 0.f;
    const float4* xr = (const float4*)(x + ((size_t)b * NNODE + p * WWID + w) * DDIM);
    float4 xa = xr[0], xb = xr[1];
    float v[8] = {z * xa.x, z * xa.y, z * xa.z, z * xa.w,
                  z * xb.x, z * xb.y, z * xb.z, z * xb.w};
    #pragma unroll
    for (int d = 0; d < 8; d++)
        #pragma unroll
        for (int o = 16; o > 0; o >>= 1) v[d] += __shfl_xor_sync(0xffffffffu, v[d], o);
    if (lane < 8) red[wrp * 8 + lane] = v[lane];
    __syncthreads();
    if (w < 8)
        g_wx[((size_t)b * PPART + p) * DDIM + w] =
            red[w] + red[8 + w] + red[16 + w] + red[24 + w];
}

// ========== kernel 5: conv + leaky 0.02 ==========
__global__ void k_y(const float* __restrict__ cw, const float* __restrict__ cb,
                    float* __restrict__ out) {
    const int b = blockIdx.x, l = threadIdx.x;
    const float* wxb = g_wx + (size_t)b * PPART * DDIM;
    float acc = cb[l];
    #pragma unroll 4
    for (int p = 0; p < PPART; p++)
        #pragma unroll
        for (int d = 0; d < 8; d++)
            acc += wxb[p * DDIM + d] * cw[l * (DDIM * PPART) + d * PPART + p];
    out[b * LL2 + l] = acc > 0.f ? acc : 0.02f * acc;
}

extern "C" void kernel_launch(void* const* d_in, const int* in_sizes, int n_in,
                              void* d_out, int out_size) {
    const float* x    = (const float*)d_in[0];
    const float* t    = (const float*)d_in[1];
    const float* cap  = (const float*)d_in[2];
    // d_in[3] = partition_index (identity; scatter folded into k_wx)
    const float* W0   = (const float*)d_in[4];
    const float* W1   = (const float*)d_in[5];
    const float* b1   = (const float*)d_in[6];
    const float* W2   = (const float*)d_in[7];
    const float* W3   = (const float*)d_in[8];
    const float* b3   = (const float*)d_in[9];
    const float* cw   = (const float*)d_in[10];
    const float* cb   = (const float*)d_in[11];
    const int* nodes  = (const int*)d_in[12];
    float* out = (float*)d_out;

    k_base<<<(PPART * I2D + 7) / 8, 256>>>(W2, b1, cap);
    k_main<<<dim3(19, PPART), 128>>>(W0, x, t, W1, nodes);
    k_z<<<dim3(8, PPART), 128>>>(W3);
    k_wx<<<dim3(PPART, BB), 128>>>(x, b3);
    k_y<<<BB, LL2>>>(cw, cb, out);
}